// round 1
// baseline (speedup 1.0000x reference)
#include <cuda_runtime.h>

// DfOp: complex order-5 causal FIR on first 96 freq bins, copy the rest.
// spec: (B=8, T=3000, F=481, 2) f32
// coef: (B=8, T=3000, NDF=96, 2*NO=10) f32
// out:  same shape as spec

#define B_DIM 8
#define T_DIM 3000
#define F_DIM 481
#define NDF 96
#define NO 5

__global__ __launch_bounds__(256) void df_kernel(
    const float* __restrict__ spec,
    const float* __restrict__ coef,
    float* __restrict__ out)
{
    const int bt = blockIdx.x;           // 0 .. B*T-1, t = bt % T within batch b
    const int t  = bt % T_DIM;

    const float2* __restrict__ spec2 = reinterpret_cast<const float2*>(spec);
    float2* __restrict__ out2        = reinterpret_cast<float2*>(out);

    const size_t row = (size_t)bt * F_DIM;

    for (int f = threadIdx.x; f < F_DIM; f += blockDim.x) {
        if (f < NDF) {
            // coefficients: 10 contiguous floats per (bt, f)
            const float* __restrict__ c = coef + ((size_t)bt * NDF + f) * (2 * NO);
            float cr[NO], ci[NO];
            #pragma unroll
            for (int k = 0; k < NO; ++k) {
                cr[k] = c[k];
                ci[k] = c[k + NO];
            }

            float fr = 0.f, fi = 0.f;
            #pragma unroll
            for (int k = 0; k < NO; ++k) {
                const int tk = t - (NO - 1) + k;       // causal tap index
                float2 x;
                if (tk >= 0) {
                    // same batch: bt - (NO-1) + k == b*T + tk
                    x = spec2[((size_t)(bt - (NO - 1) + k)) * F_DIM + f];
                } else {
                    x = make_float2(0.f, 0.f);
                }
                fr += x.x * cr[k] - x.y * ci[k];
                fi += x.x * ci[k] + x.y * cr[k];
            }
            out2[row + f] = make_float2(fr, fi);
        } else {
            out2[row + f] = spec2[row + f];
        }
    }
}

extern "C" void kernel_launch(void* const* d_in, const int* in_sizes, int n_in,
                              void* d_out, int out_size)
{
    const float* spec = (const float*)d_in[0];
    const float* coef = (const float*)d_in[1];
    float* out        = (float*)d_out;

    dim3 grid(B_DIM * T_DIM);
    dim3 block(256);
    df_kernel<<<grid, block>>>(spec, coef, out);
}